// round 1
// baseline (speedup 1.0000x reference)
#include <cuda_runtime.h>
#include <math.h>

#define Bsz   4
#define Nseq  2048
#define Dm    512
#define Hh    8
#define HDim  64
#define MLPH  2048
#define ROWS  (Bsz * Nseq)   // 8192
#define SCALE 0.125f         // HD^-0.5

// ---------------- scratch (device globals; no allocation) ----------------
__device__ float g_h[ROWS * Dm];          // LN output (reused for LN1 and LN2)
__device__ float g_qkv[ROWS * 3 * Dm];    // qkv projection
__device__ float g_attn[ROWS * Dm];       // attention output [b,n,h*64+e]
__device__ float g_x1[ROWS * Dm];         // x + attn proj (residual 1)
__device__ float g_act[ROWS * MLPH];      // gelu(fc1)

// ---------------- LayerNorm: one block per row, 128 threads ----------------
__global__ __launch_bounds__(128) void ln_kernel(
    const float* __restrict__ in, const float* __restrict__ gamma,
    const float* __restrict__ beta, float* __restrict__ out)
{
    int row = blockIdx.x;
    int tid = threadIdx.x;
    const float4* p = (const float4*)(in + (size_t)row * Dm);
    float4 v = p[tid];
    float s  = v.x + v.y + v.z + v.w;
    float ss = v.x * v.x + v.y * v.y + v.z * v.z + v.w * v.w;
    #pragma unroll
    for (int o = 16; o; o >>= 1) {
        s  += __shfl_xor_sync(0xffffffffu, s,  o);
        ss += __shfl_xor_sync(0xffffffffu, ss, o);
    }
    __shared__ float sm[8];
    int w = tid >> 5, lane = tid & 31;
    if (lane == 0) { sm[w] = s; sm[4 + w] = ss; }
    __syncthreads();
    float tot  = sm[0] + sm[1] + sm[2] + sm[3];
    float tot2 = sm[4] + sm[5] + sm[6] + sm[7];
    float mean = tot * (1.0f / Dm);
    float var  = tot2 * (1.0f / Dm) - mean * mean;
    float inv  = rsqrtf(var + 1e-5f);
    float4 g4 = ((const float4*)gamma)[tid];
    float4 b4 = ((const float4*)beta)[tid];
    float4 o;
    o.x = (v.x - mean) * inv * g4.x + b4.x;
    o.y = (v.y - mean) * inv * g4.y + b4.y;
    o.z = (v.z - mean) * inv * g4.z + b4.z;
    o.w = (v.w - mean) * inv * g4.w + b4.w;
    ((float4*)(out + (size_t)row * Dm))[tid] = o;
}

// ---------------- SGEMM: C[M,N] = A[M,K] @ W[K,N] (+bias)(+gelu)(+res) -----
// BM=BN=128, BK=16, 256 threads, 8x8 per thread.
__device__ __forceinline__ float gelu_exact(float x) {
    return 0.5f * x * (1.0f + erff(x * 0.70710678118654752f));
}

template<bool BIAS, bool GELU, bool RES>
__global__ __launch_bounds__(256) void sgemm_kernel(
    const float* __restrict__ A, const float* __restrict__ W,
    const float* __restrict__ bias, const float* __restrict__ res,
    float* __restrict__ C, int M, int N, int K)
{
    __shared__ float As[16 * 132];  // transposed [k][m], padded stride
    __shared__ float Bs[16 * 128];  // [k][n]

    int tid = threadIdx.x;
    int tx = tid & 15, ty = tid >> 4;
    int brow = blockIdx.y * 128;
    int bcol = blockIdx.x * 128;

    int ar  = tid >> 2;          // 0..63
    int ac4 = (tid & 3) << 2;    // 0,4,8,12
    int wr  = tid >> 5;          // 0..7
    int wc4 = (tid & 31) << 2;   // 0..124

    float acc[8][8];
    #pragma unroll
    for (int i = 0; i < 8; i++)
        #pragma unroll
        for (int j = 0; j < 8; j++) acc[i][j] = 0.0f;

    for (int k0 = 0; k0 < K; k0 += 16) {
        float4 a0 = *(const float4*)&A[(size_t)(brow + ar)      * K + k0 + ac4];
        float4 a1 = *(const float4*)&A[(size_t)(brow + ar + 64) * K + k0 + ac4];
        float4 b0 = *(const float4*)&W[(size_t)(k0 + wr)     * N + bcol + wc4];
        float4 b1 = *(const float4*)&W[(size_t)(k0 + wr + 8) * N + bcol + wc4];
        __syncthreads();
        As[(ac4 + 0) * 132 + ar] = a0.x;
        As[(ac4 + 1) * 132 + ar] = a0.y;
        As[(ac4 + 2) * 132 + ar] = a0.z;
        As[(ac4 + 3) * 132 + ar] = a0.w;
        As[(ac4 + 0) * 132 + ar + 64] = a1.x;
        As[(ac4 + 1) * 132 + ar + 64] = a1.y;
        As[(ac4 + 2) * 132 + ar + 64] = a1.z;
        As[(ac4 + 3) * 132 + ar + 64] = a1.w;
        *(float4*)&Bs[(wr)     * 128 + wc4] = b0;
        *(float4*)&Bs[(wr + 8) * 128 + wc4] = b1;
        __syncthreads();

        #pragma unroll
        for (int k = 0; k < 16; k++) {
            float4 x0 = *(float4*)&As[k * 132 + ty * 8];
            float4 x1 = *(float4*)&As[k * 132 + ty * 8 + 4];
            float4 y0 = *(float4*)&Bs[k * 128 + tx * 8];
            float4 y1 = *(float4*)&Bs[k * 128 + tx * 8 + 4];
            float av[8] = {x0.x, x0.y, x0.z, x0.w, x1.x, x1.y, x1.z, x1.w};
            float bv[8] = {y0.x, y0.y, y0.z, y0.w, y1.x, y1.y, y1.z, y1.w};
            #pragma unroll
            for (int i = 0; i < 8; i++)
                #pragma unroll
                for (int j = 0; j < 8; j++)
                    acc[i][j] += av[i] * bv[j];
        }
    }

    #pragma unroll
    for (int i = 0; i < 8; i++) {
        int row = brow + ty * 8 + i;
        #pragma unroll
        for (int j4 = 0; j4 < 8; j4 += 4) {
            int col = bcol + tx * 8 + j4;
            float4 v = {acc[i][j4], acc[i][j4 + 1], acc[i][j4 + 2], acc[i][j4 + 3]};
            if (BIAS) {
                float4 b = *(const float4*)&bias[col];
                v.x += b.x; v.y += b.y; v.z += b.z; v.w += b.w;
            }
            if (GELU) {
                v.x = gelu_exact(v.x); v.y = gelu_exact(v.y);
                v.z = gelu_exact(v.z); v.w = gelu_exact(v.w);
            }
            if (RES) {
                float4 r = *(const float4*)&res[(size_t)row * N + col];
                v.x += r.x; v.y += r.y; v.z += r.z; v.w += r.w;
            }
            *(float4*)&C[(size_t)row * N + col] = v;
        }
    }
}

// ---------------- Flash attention with elevation bias ----------------
// grid: (N/64, B*H). block 128 threads (16x8), each thread: 8 q-rows x 4 cols.
__global__ __launch_bounds__(128) void attn_kernel(
    const float* __restrict__ qkv, const float* __restrict__ elev,
    const float* __restrict__ alpha_p, float* __restrict__ out)
{
    __shared__ float Qs[64 * 64];  // [d][r]
    __shared__ float KP[64 * 64];  // K as [d][j], then reused as P [r][j]
    __shared__ float Vs[64 * 64];  // [j][e]

    int b  = blockIdx.y >> 3;
    int h  = blockIdx.y & 7;
    int q0 = blockIdx.x * 64;
    int tid = threadIdx.x;
    int tx = tid & 15, ty = tid >> 4;
    float alpha = alpha_p[0];

    const float* eb = elev + b * Nseq;
    const float* qbase = qkv + ((size_t)(b * Nseq + q0)) * (3 * Dm) + h * HDim;

    // load Q transposed [d][r]
    #pragma unroll
    for (int t = 0; t < 8; t++) {
        int idx = tid + t * 128;
        int r = idx & 63, d4 = (idx >> 6) << 2;
        float4 v = *(const float4*)&qbase[(size_t)r * (3 * Dm) + d4];
        Qs[(d4 + 0) * 64 + r] = v.x;
        Qs[(d4 + 1) * 64 + r] = v.y;
        Qs[(d4 + 2) * 64 + r] = v.z;
        Qs[(d4 + 3) * 64 + r] = v.w;
    }
    float eq[8];
    #pragma unroll
    for (int i = 0; i < 8; i++) eq[i] = eb[q0 + ty * 8 + i];

    float m_i[8], l_i[8], O[8][4];
    #pragma unroll
    for (int i = 0; i < 8; i++) {
        m_i[i] = -1e30f; l_i[i] = 0.0f;
        O[i][0] = O[i][1] = O[i][2] = O[i][3] = 0.0f;
    }
    __syncthreads();

    for (int m0 = 0; m0 < Nseq; m0 += 64) {
        const float* kbase = qkv + ((size_t)(b * Nseq + m0)) * (3 * Dm) + Dm + h * HDim;
        const float* vbase = kbase + Dm;

        __syncthreads();  // prev-iter reads of KP/Vs done
        // K transposed [d][j]
        #pragma unroll
        for (int t = 0; t < 8; t++) {
            int idx = tid + t * 128;
            int j = idx & 63, d4 = (idx >> 6) << 2;
            float4 v = *(const float4*)&kbase[(size_t)j * (3 * Dm) + d4];
            KP[(d4 + 0) * 64 + j] = v.x;
            KP[(d4 + 1) * 64 + j] = v.y;
            KP[(d4 + 2) * 64 + j] = v.z;
            KP[(d4 + 3) * 64 + j] = v.w;
        }
        // V direct [j][e]
        #pragma unroll
        for (int t = 0; t < 8; t++) {
            int idx = tid + t * 128;
            int j = idx >> 4, e4 = (idx & 15) << 2;
            float4 v = *(const float4*)&vbase[(size_t)j * (3 * Dm) + e4];
            *(float4*)&Vs[j * 64 + e4] = v;
        }
        float ek[4];
        #pragma unroll
        for (int jj = 0; jj < 4; jj++) ek[jj] = eb[m0 + tx * 4 + jj];
        __syncthreads();

        // S = Q K^T (scaled) + bias
        float S[8][4];
        #pragma unroll
        for (int i = 0; i < 8; i++)
            S[i][0] = S[i][1] = S[i][2] = S[i][3] = 0.0f;
        #pragma unroll 8
        for (int d = 0; d < 64; d++) {
            float4 x0 = *(float4*)&Qs[d * 64 + ty * 8];
            float4 x1 = *(float4*)&Qs[d * 64 + ty * 8 + 4];
            float4 kv = *(float4*)&KP[d * 64 + tx * 4];
            float qa[8] = {x0.x, x0.y, x0.z, x0.w, x1.x, x1.y, x1.z, x1.w};
            float kb[4] = {kv.x, kv.y, kv.z, kv.w};
            #pragma unroll
            for (int i = 0; i < 8; i++)
                #pragma unroll
                for (int j = 0; j < 4; j++)
                    S[i][j] += qa[i] * kb[j];
        }
        #pragma unroll
        for (int i = 0; i < 8; i++) {
            #pragma unroll
            for (int j = 0; j < 4; j++) {
                float diff = (ek[j] - eq[i]) * 1e-3f;
                float bias = -alpha * fmaxf(diff, 0.0f);
                bias = fminf(fmaxf(bias, -10.0f), 0.0f);
                S[i][j] = S[i][j] * SCALE + bias;
            }
        }

        // online softmax (row groups = 16 lanes sharing ty)
        #pragma unroll
        for (int i = 0; i < 8; i++) {
            float rm = fmaxf(fmaxf(S[i][0], S[i][1]), fmaxf(S[i][2], S[i][3]));
            #pragma unroll
            for (int o = 8; o; o >>= 1)
                rm = fmaxf(rm, __shfl_xor_sync(0xffffffffu, rm, o, 16));
            float mn = fmaxf(m_i[i], rm);
            float corr = __expf(m_i[i] - mn);
            m_i[i] = mn;
            float rs = 0.0f;
            #pragma unroll
            for (int j = 0; j < 4; j++) {
                S[i][j] = __expf(S[i][j] - mn);
                rs += S[i][j];
            }
            #pragma unroll
            for (int o = 8; o; o >>= 1)
                rs += __shfl_xor_sync(0xffffffffu, rs, o, 16);
            l_i[i] = l_i[i] * corr + rs;
            O[i][0] *= corr; O[i][1] *= corr; O[i][2] *= corr; O[i][3] *= corr;
        }

        __syncthreads();  // done reading KP as K
        #pragma unroll
        for (int i = 0; i < 8; i++) {
            float4 p4 = {S[i][0], S[i][1], S[i][2], S[i][3]};
            *(float4*)&KP[(ty * 8 + i) * 64 + tx * 4] = p4;
        }
        __syncthreads();  // P ready

        // O += P @ V
        #pragma unroll 8
        for (int j = 0; j < 64; j++) {
            float4 vv = *(float4*)&Vs[j * 64 + tx * 4];
            #pragma unroll
            for (int i = 0; i < 8; i++) {
                float pij = KP[(ty * 8 + i) * 64 + j];
                O[i][0] += pij * vv.x;
                O[i][1] += pij * vv.y;
                O[i][2] += pij * vv.z;
                O[i][3] += pij * vv.w;
            }
        }
    }

    #pragma unroll
    for (int i = 0; i < 8; i++) {
        float inv = 1.0f / l_i[i];
        int n = q0 + ty * 8 + i;
        float4 o = {O[i][0] * inv, O[i][1] * inv, O[i][2] * inv, O[i][3] * inv};
        *(float4*)&out[((size_t)(b * Nseq + n)) * Dm + h * HDim + tx * 4] = o;
    }
}

// ---------------- launch ----------------
extern "C" void kernel_launch(void* const* d_in, const int* in_sizes, int n_in,
                              void* d_out, int out_size)
{
    const float* x     = (const float*)d_in[0];
    const float* elev  = (const float*)d_in[1];
    const float* ln1g  = (const float*)d_in[2];
    const float* ln1b  = (const float*)d_in[3];
    const float* qkvw  = (const float*)d_in[4];
    const float* alpha = (const float*)d_in[5];
    const float* projw = (const float*)d_in[6];
    const float* projb = (const float*)d_in[7];
    const float* ln2g  = (const float*)d_in[8];
    const float* ln2b  = (const float*)d_in[9];
    const float* fc1w  = (const float*)d_in[10];
    const float* fc1b  = (const float*)d_in[11];
    const float* fc2w  = (const float*)d_in[12];
    const float* fc2b  = (const float*)d_in[13];
    float* out = (float*)d_out;

    float *ph, *pqkv, *pattn, *px1, *pact;
    cudaGetSymbolAddress((void**)&ph,    g_h);
    cudaGetSymbolAddress((void**)&pqkv,  g_qkv);
    cudaGetSymbolAddress((void**)&pattn, g_attn);
    cudaGetSymbolAddress((void**)&px1,   g_x1);
    cudaGetSymbolAddress((void**)&pact,  g_act);

    // 1. LN1
    ln_kernel<<<ROWS, 128>>>(x, ln1g, ln1b, ph);
    // 2. qkv = h @ qkv_w   [8192 x 1536 x 512]
    sgemm_kernel<false, false, false><<<dim3(12, 64), 256>>>(
        ph, qkvw, nullptr, nullptr, pqkv, ROWS, 3 * Dm, Dm);
    // 3. attention
    attn_kernel<<<dim3(Nseq / 64, Bsz * Hh), 128>>>(pqkv, elev, alpha, pattn);
    // 4. x1 = x + attn @ proj_w + proj_b   [8192 x 512 x 512]
    sgemm_kernel<true, false, true><<<dim3(4, 64), 256>>>(
        pattn, projw, projb, x, px1, ROWS, Dm, Dm);
    // 5. LN2
    ln_kernel<<<ROWS, 128>>>(px1, ln2g, ln2b, ph);
    // 6. act = gelu(h2 @ fc1_w + fc1_b)   [8192 x 2048 x 512]
    sgemm_kernel<true, true, false><<<dim3(16, 64), 256>>>(
        ph, fc1w, fc1b, nullptr, pact, ROWS, MLPH, Dm);
    // 7. out = x1 + act @ fc2_w + fc2_b   [8192 x 512 x 2048]
    sgemm_kernel<true, false, true><<<dim3(4, 64), 256>>>(
        pact, fc2w, fc2b, px1, out, ROWS, Dm, MLPH);
}

// round 2
// speedup vs baseline: 2.3821x; 2.3821x over previous
#include <cuda_runtime.h>
#include <math.h>
#include <stdint.h>

#define Bsz   4
#define Nseq  2048
#define Dm    512
#define Hh    8
#define HDim  64
#define MLPH  2048
#define ROWS  (Bsz * Nseq)   // 8192
#define SCALE 0.125f

// ---------------- scratch ----------------
__device__ float g_h[ROWS * Dm];
__device__ float g_qkv[ROWS * 3 * Dm];
__device__ float g_attn[ROWS * Dm];
__device__ float g_x1[ROWS * Dm];
__device__ float g_act[ROWS * MLPH];

// ---------------- helpers ----------------
__device__ __forceinline__ uint32_t cvt_tf32(float x) {
    uint32_t r; asm("cvt.rna.tf32.f32 %0, %1;" : "=r"(r) : "f"(x)); return r;
}
__device__ __forceinline__ uint32_t smem_u32(const void* p) {
    return (uint32_t)__cvta_generic_to_shared(p);
}
__device__ __forceinline__ void ldsm4(uint32_t r[4], uint32_t a) {
    asm volatile("ldmatrix.sync.aligned.m8n8.x4.shared.b16 {%0,%1,%2,%3}, [%4];"
        : "=r"(r[0]), "=r"(r[1]), "=r"(r[2]), "=r"(r[3]) : "r"(a));
}
__device__ __forceinline__ void mma8(float d[4], const uint32_t a[4],
                                     uint32_t b0, uint32_t b1) {
    asm volatile(
        "mma.sync.aligned.m16n8k8.row.col.f32.tf32.tf32.f32 "
        "{%0,%1,%2,%3}, {%4,%5,%6,%7}, {%8,%9}, {%0,%1,%2,%3};"
        : "+f"(d[0]), "+f"(d[1]), "+f"(d[2]), "+f"(d[3])
        : "r"(a[0]), "r"(a[1]), "r"(a[2]), "r"(a[3]), "r"(b0), "r"(b1));
}

// ---------------- LayerNorm ----------------
__global__ __launch_bounds__(128) void ln_kernel(
    const float* __restrict__ in, const float* __restrict__ gamma,
    const float* __restrict__ beta, float* __restrict__ out)
{
    int row = blockIdx.x;
    int tid = threadIdx.x;
    const float4* p = (const float4*)(in + (size_t)row * Dm);
    float4 v = p[tid];
    float s  = v.x + v.y + v.z + v.w;
    float ss = v.x * v.x + v.y * v.y + v.z * v.z + v.w * v.w;
    #pragma unroll
    for (int o = 16; o; o >>= 1) {
        s  += __shfl_xor_sync(0xffffffffu, s,  o);
        ss += __shfl_xor_sync(0xffffffffu, ss, o);
    }
    __shared__ float sm[8];
    int w = tid >> 5, lane = tid & 31;
    if (lane == 0) { sm[w] = s; sm[4 + w] = ss; }
    __syncthreads();
    float tot  = sm[0] + sm[1] + sm[2] + sm[3];
    float tot2 = sm[4] + sm[5] + sm[6] + sm[7];
    float mean = tot * (1.0f / Dm);
    float var  = tot2 * (1.0f / Dm) - mean * mean;
    float inv  = rsqrtf(var + 1e-5f);
    float4 g4 = ((const float4*)gamma)[tid];
    float4 b4 = ((const float4*)beta)[tid];
    float4 o;
    o.x = (v.x - mean) * inv * g4.x + b4.x;
    o.y = (v.y - mean) * inv * g4.y + b4.y;
    o.z = (v.z - mean) * inv * g4.z + b4.z;
    o.w = (v.w - mean) * inv * g4.w + b4.w;
    ((float4*)(out + (size_t)row * Dm))[tid] = o;
}

// ---------------- TF32 tensor-core GEMM ----------------
// C[M,N] = A[M,K] @ W[K,N] (+bias)(+gelu)(+res). 128x128 block, 256 thr.
#define AKW   20            // A smem row stride (words), padded, 16B-mult
#define BNW   132           // B smem row stride (words)
#define ASTG  (128 * AKW)   // words per A stage
#define BSTG  (16 * BNW)    // words per B stage

__device__ __forceinline__ float gelu_exact(float x) {
    return 0.5f * x * (1.0f + erff(x * 0.70710678118654752f));
}

template<bool BIAS, bool GELU, bool RES>
__global__ __launch_bounds__(256) void tgemm(
    const float* __restrict__ A, const float* __restrict__ W,
    const float* __restrict__ bias, const float* __restrict__ res,
    float* __restrict__ C, int M, int N, int K)
{
    __shared__ uint32_t As[2 * ASTG];
    __shared__ uint32_t Bs[2 * BSTG];

    int tid = threadIdx.x, lane = tid & 31, warp = tid >> 5;
    int brow = blockIdx.y * 128, bcol = blockIdx.x * 128;
    int wm = (warp >> 1) * 32, wn = (warp & 1) * 64;
    int la = lane & 7, grp = lane >> 3, g = lane >> 2, t = lane & 3;

    // gmem staging mapping
    int arow = tid >> 2, ac = (t) * 4;
    const float* Ap0 = A + (size_t)(brow + arow) * K + ac;
    const float* Ap1 = A + (size_t)(brow + arow + 64) * K + ac;
    int bk = warp;
    const float* Wp0 = W + (size_t)bk * N + bcol + lane * 4;
    const float* Wp1 = Wp0 + 8 * (size_t)N;

    uint32_t* As0 = As + arow * AKW + ac;
    uint32_t* As1 = As + (arow + 64) * AKW + ac;
    uint32_t* Bs0 = Bs + bk * BNW + lane * 4;
    uint32_t* Bs1 = Bs + (bk + 8) * BNW + lane * 4;

    // ldmatrix A addresses (per mi tile)
    uint32_t aAddr[2];
    #pragma unroll
    for (int mi = 0; mi < 2; mi++) {
        int r = wm + mi * 16 + la + (grp & 1) * 8;
        aAddr[mi] = smem_u32(As) + (uint32_t)(r * AKW + (grp >> 1) * 4) * 4u;
    }

    float acc[2][8][4];
    #pragma unroll
    for (int mi = 0; mi < 2; mi++)
        #pragma unroll
        for (int ni = 0; ni < 8; ni++)
            #pragma unroll
            for (int c = 0; c < 4; c++) acc[mi][ni][c] = 0.0f;

    int iters = K >> 4;

    float4 ra0 = *(const float4*)Ap0;
    float4 ra1 = *(const float4*)Ap1;
    float4 rb0 = *(const float4*)Wp0;
    float4 rb1 = *(const float4*)Wp1;

    // store stage 0
    {
        As0[0] = cvt_tf32(ra0.x); As0[1] = cvt_tf32(ra0.y);
        As0[2] = cvt_tf32(ra0.z); As0[3] = cvt_tf32(ra0.w);
        As1[0] = cvt_tf32(ra1.x); As1[1] = cvt_tf32(ra1.y);
        As1[2] = cvt_tf32(ra1.z); As1[3] = cvt_tf32(ra1.w);
        Bs0[0] = cvt_tf32(rb0.x); Bs0[1] = cvt_tf32(rb0.y);
        Bs0[2] = cvt_tf32(rb0.z); Bs0[3] = cvt_tf32(rb0.w);
        Bs1[0] = cvt_tf32(rb1.x); Bs1[1] = cvt_tf32(rb1.y);
        Bs1[2] = cvt_tf32(rb1.z); Bs1[3] = cvt_tf32(rb1.w);
    }
    __syncthreads();

    for (int it = 0; it < iters; ++it) {
        int s = it & 1;
        if (it + 1 < iters) {
            Ap0 += 16; Ap1 += 16; Wp0 += 16 * (size_t)N; Wp1 += 16 * (size_t)N;
            ra0 = *(const float4*)Ap0;
            ra1 = *(const float4*)Ap1;
            rb0 = *(const float4*)Wp0;
            rb1 = *(const float4*)Wp1;
        }
        // compute stage s (two k8 sub-steps)
        uint32_t sbA = (uint32_t)(s * ASTG) * 4u;
        const uint32_t* Bbase = Bs + s * BSTG;
        #pragma unroll
        for (int ks = 0; ks < 2; ks++) {
            uint32_t af[2][4];
            ldsm4(af[0], aAddr[0] + sbA + ks * 32);
            ldsm4(af[1], aAddr[1] + sbA + ks * 32);
            const uint32_t* Brow0 = Bbase + (ks * 8 + t) * BNW + wn + g;
            const uint32_t* Brow1 = Brow0 + 4 * BNW;
            #pragma unroll
            for (int ni = 0; ni < 8; ni++) {
                uint32_t b0 = Brow0[ni * 8];
                uint32_t b1 = Brow1[ni * 8];
                mma8(acc[0][ni], af[0], b0, b1);
                mma8(acc[1][ni], af[1], b0, b1);
            }
        }
        if (it + 1 < iters) {
            int q = s ^ 1;
            uint32_t* a0 = As0 + q * ASTG; uint32_t* a1 = As1 + q * ASTG;
            uint32_t* b0 = Bs0 + q * BSTG; uint32_t* b1 = Bs1 + q * BSTG;
            a0[0] = cvt_tf32(ra0.x); a0[1] = cvt_tf32(ra0.y);
            a0[2] = cvt_tf32(ra0.z); a0[3] = cvt_tf32(ra0.w);
            a1[0] = cvt_tf32(ra1.x); a1[1] = cvt_tf32(ra1.y);
            a1[2] = cvt_tf32(ra1.z); a1[3] = cvt_tf32(ra1.w);
            b0[0] = cvt_tf32(rb0.x); b0[1] = cvt_tf32(rb0.y);
            b0[2] = cvt_tf32(rb0.z); b0[3] = cvt_tf32(rb0.w);
            b1[0] = cvt_tf32(rb1.x); b1[1] = cvt_tf32(rb1.y);
            b1[2] = cvt_tf32(rb1.z); b1[3] = cvt_tf32(rb1.w);
        }
        __syncthreads();
    }

    // epilogue
    #pragma unroll
    for (int mi = 0; mi < 2; mi++) {
        int r0 = brow + wm + mi * 16 + g;
        #pragma unroll
        for (int ni = 0; ni < 8; ni++) {
            int col = bcol + wn + ni * 8 + t * 2;
            float2 v0 = {acc[mi][ni][0], acc[mi][ni][1]};
            float2 v1 = {acc[mi][ni][2], acc[mi][ni][3]};
            if (BIAS) {
                float2 bb = *(const float2*)&bias[col];
                v0.x += bb.x; v0.y += bb.y; v1.x += bb.x; v1.y += bb.y;
            }
            if (GELU) {
                v0.x = gelu_exact(v0.x); v0.y = gelu_exact(v0.y);
                v1.x = gelu_exact(v1.x); v1.y = gelu_exact(v1.y);
            }
            if (RES) {
                float2 q0 = *(const float2*)&res[(size_t)r0 * N + col];
                float2 q1 = *(const float2*)&res[(size_t)(r0 + 8) * N + col];
                v0.x += q0.x; v0.y += q0.y; v1.x += q1.x; v1.y += q1.y;
            }
            *(float2*)&C[(size_t)r0 * N + col] = v0;
            *(float2*)&C[(size_t)(r0 + 8) * N + col] = v1;
        }
    }
}

// ---------------- TF32 tensor-core flash attention ----------------
// grid (32 qtiles, 32 bh), 128 threads = 4 warps; warp owns 16 q rows.
#define KPW 68   // smem row stride (words) for K/P/Q and V

__device__ __forceinline__ float bias_f(float eq, float ek, float alpha) {
    float diff = (ek - eq) * 1e-3f;
    float b = -alpha * fmaxf(diff, 0.0f);
    return fminf(fmaxf(b, -10.0f), 0.0f);
}

__global__ __launch_bounds__(128) void attn_tc(
    const float* __restrict__ qkv, const float* __restrict__ elev,
    const float* __restrict__ alpha_p, float* __restrict__ out)
{
    __shared__ uint32_t sKP[64 * KPW];  // K tile, then reused for P
    __shared__ uint32_t sV[64 * KPW];   // V tile [key][e]
    __shared__ float sEK[64];

    int b = blockIdx.y >> 3, h = blockIdx.y & 7;
    int q0 = blockIdx.x * 64;
    int tid = threadIdx.x, lane = tid & 31, warp = tid >> 5;
    int la = lane & 7, grp = lane >> 3, g = lane >> 2, t = lane & 3;
    float alpha = alpha_p[0];
    const float* eb = elev + b * Nseq;
    const float* qbase = qkv + ((size_t)(b * Nseq + q0)) * (3 * Dm) + h * HDim;

    // stage Q through sKP
    #pragma unroll
    for (int i = 0; i < 8; i++) {
        int idx = tid + i * 128;
        int r = idx >> 4, c4 = (idx & 15) * 4;
        float4 v = *(const float4*)&qbase[(size_t)r * (3 * Dm) + c4];
        uint32_t* d = &sKP[r * KPW + c4];
        d[0] = cvt_tf32(v.x); d[1] = cvt_tf32(v.y);
        d[2] = cvt_tf32(v.z); d[3] = cvt_tf32(v.w);
    }
    __syncthreads();

    int qr0 = warp * 16;
    uint32_t aAddr = smem_u32(sKP) +
        (uint32_t)((qr0 + la + (grp & 1) * 8) * KPW + (grp >> 1) * 4) * 4u;

    uint32_t qf[8][4];
    #pragma unroll
    for (int kc = 0; kc < 8; kc++) ldsm4(qf[kc], aAddr + kc * 32);

    float eq0 = eb[q0 + qr0 + g];
    float eq1 = eb[q0 + qr0 + g + 8];

    uint32_t bAddr[4];
    #pragma unroll
    for (int nt = 0; nt < 4; nt++) {
        int r = nt * 16 + la + (grp >> 1) * 8;
        bAddr[nt] = smem_u32(sKP) + (uint32_t)(r * KPW + (grp & 1) * 4) * 4u;
    }

    float O[8][4];
    #pragma unroll
    for (int e = 0; e < 8; e++)
        O[e][0] = O[e][1] = O[e][2] = O[e][3] = 0.0f;
    float mi0 = -1e30f, mi1 = -1e30f, li0 = 0.0f, li1 = 0.0f;

    for (int m0 = 0; m0 < Nseq; m0 += 64) {
        __syncthreads();   // prior tile fully consumed
        const float* kb = qkv + ((size_t)(b * Nseq + m0)) * (3 * Dm) + Dm + h * HDim;
        const float* vb = kb + Dm;
        #pragma unroll
        for (int i = 0; i < 8; i++) {
            int idx = tid + i * 128;
            int r = idx >> 4, c4 = (idx & 15) * 4;
            float4 kv = *(const float4*)&kb[(size_t)r * (3 * Dm) + c4];
            float4 vv = *(const float4*)&vb[(size_t)r * (3 * Dm) + c4];
            uint32_t* dk = &sKP[r * KPW + c4];
            uint32_t* dv = &sV[r * KPW + c4];
            dk[0] = cvt_tf32(kv.x); dk[1] = cvt_tf32(kv.y);
            dk[2] = cvt_tf32(kv.z); dk[3] = cvt_tf32(kv.w);
            dv[0] = cvt_tf32(vv.x); dv[1] = cvt_tf32(vv.y);
            dv[2] = cvt_tf32(vv.z); dv[3] = cvt_tf32(vv.w);
        }
        if (tid < 64) sEK[tid] = eb[m0 + tid];
        __syncthreads();

        // S = Q K^T
        float S[8][4];
        #pragma unroll
        for (int nt = 0; nt < 8; nt++)
            S[nt][0] = S[nt][1] = S[nt][2] = S[nt][3] = 0.0f;
        #pragma unroll
        for (int kc = 0; kc < 8; kc++) {
            #pragma unroll
            for (int nt4 = 0; nt4 < 4; nt4++) {
                uint32_t bf[4];
                ldsm4(bf, bAddr[nt4] + kc * 32);
                mma8(S[nt4 * 2], qf[kc], bf[0], bf[1]);
                mma8(S[nt4 * 2 + 1], qf[kc], bf[2], bf[3]);
            }
        }

        // bias + online softmax
        float rm0 = -1e30f, rm1 = -1e30f;
        #pragma unroll
        for (int nt = 0; nt < 8; nt++) {
            float ek0 = sEK[nt * 8 + t * 2];
            float ek1 = sEK[nt * 8 + t * 2 + 1];
            S[nt][0] = S[nt][0] * SCALE + bias_f(eq0, ek0, alpha);
            S[nt][1] = S[nt][1] * SCALE + bias_f(eq0, ek1, alpha);
            S[nt][2] = S[nt][2] * SCALE + bias_f(eq1, ek0, alpha);
            S[nt][3] = S[nt][3] * SCALE + bias_f(eq1, ek1, alpha);
            rm0 = fmaxf(rm0, fmaxf(S[nt][0], S[nt][1]));
            rm1 = fmaxf(rm1, fmaxf(S[nt][2], S[nt][3]));
        }
        rm0 = fmaxf(rm0, __shfl_xor_sync(0xffffffffu, rm0, 1));
        rm0 = fmaxf(rm0, __shfl_xor_sync(0xffffffffu, rm0, 2));
        rm1 = fmaxf(rm1, __shfl_xor_sync(0xffffffffu, rm1, 1));
        rm1 = fmaxf(rm1, __shfl_xor_sync(0xffffffffu, rm1, 2));
        float mn0 = fmaxf(mi0, rm0), mn1 = fmaxf(mi1, rm1);
        float c0 = __expf(mi0 - mn0), c1 = __expf(mi1 - mn1);
        mi0 = mn0; mi1 = mn1;
        float rs0 = 0.0f, rs1 = 0.0f;
        #pragma unroll
        for (int nt = 0; nt < 8; nt++) {
            S[nt][0] = __expf(S[nt][0] - mn0); rs0 += S[nt][0];
            S[nt][1] = __expf(S[nt][1] - mn0); rs0 += S[nt][1];
            S[nt][2] = __expf(S[nt][2] - mn1); rs1 += S[nt][2];
            S[nt][3] = __expf(S[nt][3] - mn1); rs1 += S[nt][3];
        }
        rs0 += __shfl_xor_sync(0xffffffffu, rs0, 1);
        rs0 += __shfl_xor_sync(0xffffffffu, rs0, 2);
        rs1 += __shfl_xor_sync(0xffffffffu, rs1, 1);
        rs1 += __shfl_xor_sync(0xffffffffu, rs1, 2);
        li0 = li0 * c0 + rs0;
        li1 = li1 * c1 + rs1;
        #pragma unroll
        for (int e = 0; e < 8; e++) {
            O[e][0] *= c0; O[e][1] *= c0; O[e][2] *= c1; O[e][3] *= c1;
        }

        __syncthreads();   // all warps done reading K from sKP

        // store P (tf32) into own 16 rows of sKP
        #pragma unroll
        for (int nt = 0; nt < 8; nt++) {
            uint32_t* p0 = &sKP[(qr0 + g) * KPW + nt * 8 + t * 2];
            uint32_t* p1 = &sKP[(qr0 + 8 + g) * KPW + nt * 8 + t * 2];
            p0[0] = cvt_tf32(S[nt][0]); p0[1] = cvt_tf32(S[nt][1]);
            p1[0] = cvt_tf32(S[nt][2]); p1[1] = cvt_tf32(S[nt][3]);
        }
        __syncwarp();

        // O += P @ V
        #pragma unroll
        for (int kc = 0; kc < 8; kc++) {
            uint32_t pf[4];
            ldsm4(pf, aAddr + kc * 32);
            const uint32_t* v0 = &sV[(kc * 8 + t) * KPW + g];
            const uint32_t* v1 = v0 + 4 * KPW;
            #pragma unroll
            for (int e = 0; e < 8; e++)
                mma8(O[e], pf, v0[e * 8], v1[e * 8]);
        }
    }

    float inv0 = 1.0f / li0, inv1 = 1.0f / li1;
    int row0 = b * Nseq + q0 + qr0 + g;
    #pragma unroll
    for (int e = 0; e < 8; e++) {
        int col = h * HDim + e * 8 + t * 2;
        float2 o0 = {O[e][0] * inv0, O[e][1] * inv0};
        float2 o1 = {O[e][2] * inv1, O[e][3] * inv1};
        *(float2*)&out[(size_t)row0 * Dm + col] = o0;
        *(float2*)&out[(size_t)(row0 + 8) * Dm + col] = o1;
    }
}

// ---------------- launch ----------------
extern "C" void kernel_launch(void* const* d_in, const int* in_sizes, int n_in,
                              void* d_out, int out_size)
{
    const float* x     = (const float*)d_in[0];
    const float* elev  = (const float*)d_in[1];
    const float* ln1g  = (const float*)d_in[2];
    const float* ln1b  = (const float*)d_in[3];
    const float* qkvw  = (const float*)d_in[4];
    const float* alpha = (const float*)d_in[5];
    const float* projw = (const float*)d_in[6];
    const float* projb = (const float*)d_in[7];
    const float* ln2g  = (const float*)d_in[8];
    const float* ln2b  = (const float*)d_in[9];
    const float* fc1w  = (const float*)d_in[10];
    const float* fc1b  = (const float*)d_in[11];
    const float* fc2w  = (const float*)d_in[12];
    const float* fc2b  = (const float*)d_in[13];
    float* out = (float*)d_out;

    float *ph, *pqkv, *pattn, *px1, *pact;
    cudaGetSymbolAddress((void**)&ph,    g_h);
    cudaGetSymbolAddress((void**)&pqkv,  g_qkv);
    cudaGetSymbolAddress((void**)&pattn, g_attn);
    cudaGetSymbolAddress((void**)&px1,   g_x1);
    cudaGetSymbolAddress((void**)&pact,  g_act);

    // 1. LN1
    ln_kernel<<<ROWS, 128>>>(x, ln1g, ln1b, ph);
    // 2. qkv = h @ qkv_w   [8192 x 1536 x 512]
    tgemm<false, false, false><<<dim3(12, 64), 256>>>(
        ph, qkvw, nullptr, nullptr, pqkv, ROWS, 3 * Dm, Dm);
    // 3. attention
    attn_tc<<<dim3(Nseq / 64, Bsz * Hh), 128>>>(pqkv, elev, alpha, pattn);
    // 4. x1 = x + attn @ proj_w + proj_b
    tgemm<true, false, true><<<dim3(4, 64), 256>>>(
        pattn, projw, projb, x, px1, ROWS, Dm, Dm);
    // 5. LN2
    ln_kernel<<<ROWS, 128>>>(px1, ln2g, ln2b, ph);
    // 6. act = gelu(h2 @ fc1_w + fc1_b)
    tgemm<true, true, false><<<dim3(16, 64), 256>>>(
        ph, fc1w, fc1b, nullptr, pact, ROWS, MLPH, Dm);
    // 7. out = x1 + act @ fc2_w + fc2_b
    tgemm<true, false, true><<<dim3(4, 64), 256>>>(
        pact, fc2w, fc2b, px1, out, ROWS, Dm, MLPH);
}

// round 3
// speedup vs baseline: 2.9331x; 1.2313x over previous
#include <cuda_runtime.h>
#include <math.h>
#include <stdint.h>

#define Bsz   4
#define Nseq  2048
#define Dm    512
#define Hh    8
#define HDim  64
#define MLPH  2048
#define ROWS  (Bsz * Nseq)
#define SCALE 0.125f

// ---------------- scratch ----------------
__device__ float g_h[ROWS * Dm];
__device__ float g_qkv[ROWS * 3 * Dm];
__device__ float g_attn[ROWS * Dm];
__device__ float g_x1[ROWS * Dm];
__device__ float g_act[ROWS * MLPH];
__device__ float g_wt[3145728];   // transposed+tf32 weights
#define WT_QKV  0
#define WT_PROJ 786432
#define WT_FC1  1048576
#define WT_FC2  2097152

// ---------------- helpers ----------------
__device__ __forceinline__ uint32_t cvt_tf32(float x) {
    uint32_t r; asm("cvt.rna.tf32.f32 %0, %1;" : "=r"(r) : "f"(x)); return r;
}
__device__ __forceinline__ float round_tf32(float x) {
    return __uint_as_float(cvt_tf32(x));
}
__device__ __forceinline__ uint32_t smem_u32(const void* p) {
    return (uint32_t)__cvta_generic_to_shared(p);
}
__device__ __forceinline__ void ldsm4(uint32_t r[4], uint32_t a) {
    asm volatile("ldmatrix.sync.aligned.m8n8.x4.shared.b16 {%0,%1,%2,%3}, [%4];"
        : "=r"(r[0]), "=r"(r[1]), "=r"(r[2]), "=r"(r[3]) : "r"(a));
}
__device__ __forceinline__ void mma8(float d[4], const uint32_t a[4],
                                     uint32_t b0, uint32_t b1) {
    asm volatile(
        "mma.sync.aligned.m16n8k8.row.col.f32.tf32.tf32.f32 "
        "{%0,%1,%2,%3}, {%4,%5,%6,%7}, {%8,%9}, {%0,%1,%2,%3};"
        : "+f"(d[0]), "+f"(d[1]), "+f"(d[2]), "+f"(d[3])
        : "r"(a[0]), "r"(a[1]), "r"(a[2]), "r"(a[3]), "r"(b0), "r"(b1));
}
__device__ __forceinline__ void cpa16(uint32_t dst, const void* src) {
    asm volatile("cp.async.cg.shared.global [%0], [%1], 16;\n"
        :: "r"(dst), "l"(src));
}
#define CP_COMMIT() asm volatile("cp.async.commit_group;\n" ::: "memory")
#define CP_WAIT1()  asm volatile("cp.async.wait_group 1;\n" ::: "memory")

// ---------------- weight transpose + tf32 round (once per launch) ---------
__global__ __launch_bounds__(256) void transpose_cvt(
    const float* __restrict__ in, float* __restrict__ out, int K, int N)
{
    __shared__ float t[32][33];
    int n0 = blockIdx.x * 32, k0 = blockIdx.y * 32;
    int tx = threadIdx.x, ty = threadIdx.y;  // 32 x 8
    #pragma unroll
    for (int j = 0; j < 32; j += 8)
        t[ty + j][tx] = in[(size_t)(k0 + ty + j) * N + n0 + tx];
    __syncthreads();
    #pragma unroll
    for (int j = 0; j < 32; j += 8)
        out[(size_t)(n0 + ty + j) * K + k0 + tx] = round_tf32(t[tx][ty + j]);
}

// ---------------- LayerNorm (emits tf32-rounded output) ----------------
__global__ __launch_bounds__(128) void ln_kernel(
    const float* __restrict__ in, const float* __restrict__ gamma,
    const float* __restrict__ beta, float* __restrict__ out)
{
    int row = blockIdx.x;
    int tid = threadIdx.x;
    const float4* p = (const float4*)(in + (size_t)row * Dm);
    float4 v = p[tid];
    float s  = v.x + v.y + v.z + v.w;
    float ss = v.x * v.x + v.y * v.y + v.z * v.z + v.w * v.w;
    #pragma unroll
    for (int o = 16; o; o >>= 1) {
        s  += __shfl_xor_sync(0xffffffffu, s,  o);
        ss += __shfl_xor_sync(0xffffffffu, ss, o);
    }
    __shared__ float sm[8];
    int w = tid >> 5, lane = tid & 31;
    if (lane == 0) { sm[w] = s; sm[4 + w] = ss; }
    __syncthreads();
    float tot  = sm[0] + sm[1] + sm[2] + sm[3];
    float tot2 = sm[4] + sm[5] + sm[6] + sm[7];
    float mean = tot * (1.0f / Dm);
    float var  = tot2 * (1.0f / Dm) - mean * mean;
    float inv  = rsqrtf(var + 1e-5f);
    float4 g4 = ((const float4*)gamma)[tid];
    float4 b4 = ((const float4*)beta)[tid];
    float4 o;
    o.x = round_tf32((v.x - mean) * inv * g4.x + b4.x);
    o.y = round_tf32((v.y - mean) * inv * g4.y + b4.y);
    o.z = round_tf32((v.z - mean) * inv * g4.z + b4.z);
    o.w = round_tf32((v.w - mean) * inv * g4.w + b4.w);
    ((float4*)(out + (size_t)row * Dm))[tid] = o;
}

// ---------------- TF32 GEMM: all-ldmatrix, cp.async 3-stage ----------------
// A [M,K] tf32-rounded fp32, WT [N,K] tf32. 128x128 block, 256 thr.
// smem layout per stage: 128 rows x 16 words, XOR-swizzled:
//   phys(row,k) = row*16 + (((k>>2) ^ ((row>>1)&3))<<2) + (k&3)
#define STG_B 8192           // bytes per (A or B) stage
#define BOFF  24576          // B region byte offset (3 A stages)

__device__ __forceinline__ float gelu_exact(float x) {
    return 0.5f * x * (1.0f + erff(x * 0.70710678118654752f));
}

template<int N, int K, bool BIAS, bool GELU, bool RES, bool ROUND>
__global__ __launch_bounds__(256, 2) void tgemm(
    const float* __restrict__ A, const float* __restrict__ WT,
    const float* __restrict__ bias, const float* __restrict__ res,
    float* __restrict__ C)
{
    __shared__ uint32_t smbuf[12288];   // 48KB: A[3][2048] + B[3][2048]
    uint32_t smb = smem_u32(smbuf);

    int tid = threadIdx.x, lane = tid & 31, warp = tid >> 5;
    int brow = blockIdx.y * 128, bcol = blockIdx.x * 128;
    int wm = (warp >> 1) * 32, wn = (warp & 1) * 64;
    int la = lane & 7, grp = lane >> 3, g = lane >> 2, t = lane & 3;

    // --- staging mapping: thread -> (row tid>>2 [+64], k-group tid&3) ---
    int m0 = tid >> 2, t4 = tid & 3;
    const float* Ag0 = A  + (size_t)(brow + m0) * K + t4 * 4;
    const float* Ag1 = Ag0 + (size_t)64 * K;
    const float* Bg0 = WT + (size_t)(bcol + m0) * K + t4 * 4;
    const float* Bg1 = Bg0 + (size_t)64 * K;
    uint32_t dA0 = smb + (uint32_t)(m0 * 16 + ((t4 ^ ((m0 >> 1) & 3)) << 2)) * 4u;
    uint32_t dA1 = dA0 + 4096;   // row+64: same swizzle ((m0+64)>>1)&3 == (m0>>1)&3
    uint32_t dB0 = dA0 + BOFF;
    uint32_t dB1 = dB0 + 4096;

    // --- ldmatrix lane addresses ---
    uint32_t aAddr[2];
    #pragma unroll
    for (int mi = 0; mi < 2; mi++) {
        int r = wm + mi * 16 + la + (grp & 1) * 8;
        int c = grp >> 1;
        int ph = c ^ ((r >> 1) & 3);
        aAddr[mi] = smb + (uint32_t)(r * 64 + (ph << 4));
    }
    uint32_t bAddr;
    {
        int n = wn + (lane & 7) + ((lane >> 4) & 1) * 8;
        int c = (lane >> 3) & 1;
        int ph = c ^ ((n >> 1) & 3);
        bAddr = smb + BOFF + (uint32_t)(n * 64 + (ph << 4));
    }

    float acc[2][8][4];
    #pragma unroll
    for (int mi = 0; mi < 2; mi++)
        #pragma unroll
        for (int ni = 0; ni < 8; ni++)
            #pragma unroll
            for (int c = 0; c < 4; c++) acc[mi][ni][c] = 0.0f;

    constexpr int iters = K / 16;

    // prologue: prefetch iters 0,1
    #pragma unroll
    for (int p = 0; p < 2; p++) {
        uint32_t o = p * STG_B;
        size_t ko = (size_t)p * 16;
        cpa16(dA0 + o, Ag0 + ko); cpa16(dA1 + o, Ag1 + ko);
        cpa16(dB0 + o, Bg0 + ko); cpa16(dB1 + o, Bg1 + ko);
        CP_COMMIT();
    }

    #pragma unroll 1
    for (int it = 0; it < iters; ++it) {
        CP_WAIT1();
        __syncthreads();
        if (it + 2 < iters) {
            int sp = (it + 2) % 3;
            uint32_t o = sp * STG_B;
            size_t ko = (size_t)(it + 2) * 16;
            cpa16(dA0 + o, Ag0 + ko); cpa16(dA1 + o, Ag1 + ko);
            cpa16(dB0 + o, Bg0 + ko); cpa16(dB1 + o, Bg1 + ko);
        }
        CP_COMMIT();

        uint32_t so = (uint32_t)((it % 3) * STG_B);
        #pragma unroll
        for (int ks = 0; ks < 2; ks++) {
            uint32_t kx = (uint32_t)(ks << 5);
            uint32_t af0[4], af1[4];
            ldsm4(af0, (aAddr[0] + so) ^ kx);
            ldsm4(af1, (aAddr[1] + so) ^ kx);
            #pragma unroll
            for (int ng = 0; ng < 4; ng++) {
                uint32_t bf[4];
                ldsm4(bf, (bAddr + so + ng * 1024) ^ kx);
                mma8(acc[0][ng * 2],     af0, bf[0], bf[1]);
                mma8(acc[0][ng * 2 + 1], af0, bf[2], bf[3]);
                mma8(acc[1][ng * 2],     af1, bf[0], bf[1]);
                mma8(acc[1][ng * 2 + 1], af1, bf[2], bf[3]);
            }
        }
    }

    // epilogue
    #pragma unroll
    for (int mi = 0; mi < 2; mi++) {
        int r0 = brow + wm + mi * 16 + g;
        #pragma unroll
        for (int ni = 0; ni < 8; ni++) {
            int col = bcol + wn + ni * 8 + t * 2;
            float2 v0 = {acc[mi][ni][0], acc[mi][ni][1]};
            float2 v1 = {acc[mi][ni][2], acc[mi][ni][3]};
            if (BIAS) {
                float2 bb = *(const float2*)&bias[col];
                v0.x += bb.x; v0.y += bb.y; v1.x += bb.x; v1.y += bb.y;
            }
            if (GELU) {
                v0.x = gelu_exact(v0.x); v0.y = gelu_exact(v0.y);
                v1.x = gelu_exact(v1.x); v1.y = gelu_exact(v1.y);
            }
            if (RES) {
                float2 q0 = *(const float2*)&res[(size_t)r0 * N + col];
                float2 q1 = *(const float2*)&res[(size_t)(r0 + 8) * N + col];
                v0.x += q0.x; v0.y += q0.y; v1.x += q1.x; v1.y += q1.y;
            }
            if (ROUND) {
                v0.x = round_tf32(v0.x); v0.y = round_tf32(v0.y);
                v1.x = round_tf32(v1.x); v1.y = round_tf32(v1.y);
            }
            *(float2*)&C[(size_t)r0 * N + col] = v0;
            *(float2*)&C[(size_t)(r0 + 8) * N + col] = v1;
        }
    }
}

// ---------------- TF32 tensor-core flash attention ----------------
#define KPW 68

__device__ __forceinline__ float bias_f(float eq, float ek, float alpha) {
    float diff = (ek - eq) * 1e-3f;
    float b = -alpha * fmaxf(diff, 0.0f);
    return fminf(fmaxf(b, -10.0f), 0.0f);
}

__global__ __launch_bounds__(128) void attn_tc(
    const float* __restrict__ qkv, const float* __restrict__ elev,
    const float* __restrict__ alpha_p, float* __restrict__ out)
{
    __shared__ uint32_t sKP[64 * KPW];
    __shared__ uint32_t sV[64 * KPW];
    __shared__ float sEK[64];

    int b = blockIdx.y >> 3, h = blockIdx.y & 7;
    int q0 = blockIdx.x * 64;
    int tid = threadIdx.x, lane = tid & 31, warp = tid >> 5;
    int la = lane & 7, grp = lane >> 3, g = lane >> 2, t = lane & 3;
    float alpha = alpha_p[0];
    const float* eb = elev + b * Nseq;
    const float* qbase = qkv + ((size_t)(b * Nseq + q0)) * (3 * Dm) + h * HDim;

    #pragma unroll
    for (int i = 0; i < 8; i++) {
        int idx = tid + i * 128;
        int r = idx >> 4, c4 = (idx & 15) * 4;
        float4 v = *(const float4*)&qbase[(size_t)r * (3 * Dm) + c4];
        uint32_t* d = &sKP[r * KPW + c4];
        d[0] = cvt_tf32(v.x); d[1] = cvt_tf32(v.y);
        d[2] = cvt_tf32(v.z); d[3] = cvt_tf32(v.w);
    }
    __syncthreads();

    int qr0 = warp * 16;
    uint32_t aAddr = smem_u32(sKP) +
        (uint32_t)((qr0 + la + (grp & 1) * 8) * KPW + (grp >> 1) * 4) * 4u;

    uint32_t qf[8][4];
    #pragma unroll
    for (int kc = 0; kc < 8; kc++) ldsm4(qf[kc], aAddr + kc * 32);

    float eq0 = eb[q0 + qr0 + g];
    float eq1 = eb[q0 + qr0 + g + 8];

    uint32_t bAddr[4];
    #pragma unroll
    for (int nt = 0; nt < 4; nt++) {
        int r = nt * 16 + la + (grp >> 1) * 8;
        bAddr[nt] = smem_u32(sKP) + (uint32_t)(r * KPW + (grp & 1) * 4) * 4u;
    }

    float O[8][4];
    #pragma unroll
    for (int e = 0; e < 8; e++)
        O[e][0] = O[e][1] = O[e][2] = O[e][3] = 0.0f;
    float mi0 = -1e30f, mi1 = -1e30f, li0 = 0.0f, li1 = 0.0f;

    for (int m0 = 0; m0 < Nseq; m0 += 64) {
        __syncthreads();
        const float* kb = qkv + ((size_t)(b * Nseq + m0)) * (3 * Dm) + Dm + h * HDim;
        const float* vb = kb + Dm;
        #pragma unroll
        for (int i = 0; i < 8; i++) {
            int idx = tid + i * 128;
            int r = idx >> 4, c4 = (idx & 15) * 4;
            float4 kv = *(const float4*)&kb[(size_t)r * (3 * Dm) + c4];
            float4 vv = *(const float4*)&vb[(size_t)r * (3 * Dm) + c4];
            uint32_t* dk = &sKP[r * KPW + c4];
            uint32_t* dv = &sV[r * KPW + c4];
            dk[0] = cvt_tf32(kv.x); dk[1] = cvt_tf32(kv.y);
            dk[2] = cvt_tf32(kv.z); dk[3] = cvt_tf32(kv.w);
            dv[0] = cvt_tf32(vv.x); dv[1] = cvt_tf32(vv.y);
            dv[2] = cvt_tf32(vv.z); dv[3] = cvt_tf32(vv.w);
        }
        if (tid < 64) sEK[tid] = eb[m0 + tid];
        __syncthreads();

        float S[8][4];
        #pragma unroll
        for (int nt = 0; nt < 8; nt++)
            S[nt][0] = S[nt][1] = S[nt][2] = S[nt][3] = 0.0f;
        #pragma unroll
        for (int kc = 0; kc < 8; kc++) {
            #pragma unroll
            for (int nt4 = 0; nt4 < 4; nt4++) {
                uint32_t bf[4];
                ldsm4(bf, bAddr[nt4] + kc * 32);
                mma8(S[nt4 * 2], qf[kc], bf[0], bf[1]);
                mma8(S[nt4 * 2 + 1], qf[kc], bf[2], bf[3]);
            }
        }

        float rm0 = -1e30f, rm1 = -1e30f;
        #pragma unroll
        for (int nt = 0; nt < 8; nt++) {
            float ek0 = sEK[nt * 8 + t * 2];
            float ek1 = sEK[nt * 8 + t * 2 + 1];
            S[nt][0] = S[nt][0] * SCALE + bias_f(eq0, ek0, alpha);
            S[nt][1] = S[nt][1] * SCALE + bias_f(eq0, ek1, alpha);
            S[nt][2] = S[nt][2] * SCALE + bias_f(eq1, ek0, alpha);
            S[nt][3] = S[nt][3] * SCALE + bias_f(eq1, ek1, alpha);
            rm0 = fmaxf(rm0, fmaxf(S[nt][0], S[nt][1]));
            rm1 = fmaxf(rm1, fmaxf(S[nt][2], S[nt][3]));
        }
        rm0 = fmaxf(rm0, __shfl_xor_sync(0xffffffffu, rm0, 1));
        rm0 = fmaxf(rm0, __shfl_xor_sync(0xffffffffu, rm0, 2));
        rm1 = fmaxf(rm1, __shfl_xor_sync(0xffffffffu, rm1, 1));
        rm1 = fmaxf(rm1, __shfl_xor_sync(0xffffffffu, rm1, 2));
        float mn0 = fmaxf(mi0, rm0), mn1 = fmaxf(mi1, rm1);
        float c0 = __expf(mi0 - mn0), c1 = __expf(mi1 - mn1);
        mi0 = mn0; mi1 = mn1;
        float rs0 = 0.0f, rs1 = 0.0f;
        #pragma unroll
        for (int nt = 0; nt < 8; nt++) {
            S[nt][0] = __expf(S[nt][0] - mn0); rs0 += S[nt][0];
            S[nt][1] = __expf(S[nt][1] - mn0); rs0 += S[nt][1];
            S[nt][2] = __expf(S[nt][2] - mn1); rs1 += S[nt][2];
            S[nt][3] = __expf(S[nt][3] - mn1); rs1 += S[nt][3];
        }
        rs0 += __shfl_xor_sync(0xffffffffu, rs0, 1);
        rs0 += __shfl_xor_sync(0xffffffffu, rs0, 2);
        rs1 += __shfl_xor_sync(0xffffffffu, rs1, 1);
        rs1 += __shfl_xor_sync(0xffffffffu, rs1, 2);
        li0 = li0 * c0 + rs0;
        li1 = li1 * c1 + rs1;
        #pragma unroll
        for (int e = 0; e < 8; e++) {
            O[e][0] *= c0; O[e][1] *= c0; O[e][2] *= c1; O[e][3] *= c1;
        }

        __syncthreads();

        #pragma unroll
        for (int nt = 0; nt < 8; nt++) {
            uint32_t* p0 = &sKP[(qr0 + g) * KPW + nt * 8 + t * 2];
            uint32_t* p1 = &sKP[(qr0 + 8 + g) * KPW + nt * 8 + t * 2];
            p0[0] = cvt_tf32(S[nt][0]); p0[1] = cvt_tf32(S[nt][1]);
            p1[0] = cvt_tf32(S[nt][2]); p1[1] = cvt_tf32(S[nt][3]);
        }
        __syncwarp();

        #pragma unroll
        for (int kc = 0; kc < 8; kc++) {
            uint32_t pf[4];
            ldsm4(pf, aAddr + kc * 32);
            const uint32_t* v0 = &sV[(kc * 8 + t) * KPW + g];
            const uint32_t* v1 = v0 + 4 * KPW;
            #pragma unroll
            for (int e = 0; e < 8; e++)
                mma8(O[e], pf, v0[e * 8], v1[e * 8]);
        }
    }

    float inv0 = 1.0f / li0, inv1 = 1.0f / li1;
    int row0 = b * Nseq + q0 + qr0 + g;
    #pragma unroll
    for (int e = 0; e < 8; e++) {
        int col = h * HDim + e * 8 + t * 2;
        float2 o0 = {round_tf32(O[e][0] * inv0), round_tf32(O[e][1] * inv0)};
        float2 o1 = {round_tf32(O[e][2] * inv1), round_tf32(O[e][3] * inv1)};
        *(float2*)&out[(size_t)row0 * Dm + col] = o0;
        *(float2*)&out[(size_t)(row0 + 8) * Dm + col] = o1;
    }
}

// ---------------- launch ----------------
extern "C" void kernel_launch(void* const* d_in, const int* in_sizes, int n_in,
                              void* d_out, int out_size)
{
    const float* x     = (const float*)d_in[0];
    const float* elev  = (const float*)d_in[1];
    const float* ln1g  = (const float*)d_in[2];
    const float* ln1b  = (const float*)d_in[3];
    const float* qkvw  = (const float*)d_in[4];
    const float* alpha = (const float*)d_in[5];
    const float* projw = (const float*)d_in[6];
    const float* projb = (const float*)d_in[7];
    const float* ln2g  = (const float*)d_in[8];
    const float* ln2b  = (const float*)d_in[9];
    const float* fc1w  = (const float*)d_in[10];
    const float* fc1b  = (const float*)d_in[11];
    const float* fc2w  = (const float*)d_in[12];
    const float* fc2b  = (const float*)d_in[13];
    float* out = (float*)d_out;

    float *ph, *pqkv, *pattn, *px1, *pact, *pwt;
    cudaGetSymbolAddress((void**)&ph,    g_h);
    cudaGetSymbolAddress((void**)&pqkv,  g_qkv);
    cudaGetSymbolAddress((void**)&pattn, g_attn);
    cudaGetSymbolAddress((void**)&px1,   g_x1);
    cudaGetSymbolAddress((void**)&pact,  g_act);
    cudaGetSymbolAddress((void**)&pwt,   g_wt);

    // 0. transpose + round all weights into [n][k] tf32 scratch
    transpose_cvt<<<dim3(48, 16), dim3(32, 8)>>>(qkvw,  pwt + WT_QKV,  Dm,   3 * Dm);
    transpose_cvt<<<dim3(16, 16), dim3(32, 8)>>>(projw, pwt + WT_PROJ, Dm,   Dm);
    transpose_cvt<<<dim3(64, 16), dim3(32, 8)>>>(fc1w,  pwt + WT_FC1,  Dm,   MLPH);
    transpose_cvt<<<dim3(16, 64), dim3(32, 8)>>>(fc2w,  pwt + WT_FC2,  MLPH, Dm);

    // 1. LN1 (tf32-rounded output)
    ln_kernel<<<ROWS, 128>>>(x, ln1g, ln1b, ph);
    // 2. qkv = h @ qkv_w
    tgemm<1536, 512, false, false, false, false><<<dim3(12, 64), 256>>>(
        ph, pwt + WT_QKV, nullptr, nullptr, pqkv);
    // 3. attention (tf32-rounded output)
    attn_tc<<<dim3(Nseq / 64, Bsz * Hh), 128>>>(pqkv, elev, alpha, pattn);
    // 4. x1 = x + attn @ proj_w + proj_b
    tgemm<512, 512, true, false, true, false><<<dim3(4, 64), 256>>>(
        pattn, pwt + WT_PROJ, projb, x, px1);
    // 5. LN2 (tf32-rounded output)
    ln_kernel<<<ROWS, 128>>>(px1, ln2g, ln2b, ph);
    // 6. act = gelu(h2 @ fc1_w + fc1_b)  (tf32-rounded output)
    tgemm<2048, 512, true, true, false, true><<<dim3(16, 64), 256>>>(
        ph, pwt + WT_FC1, fc1b, nullptr, pact);
    // 7. out = x1 + act @ fc2_w + fc2_b
    tgemm<512, 2048, true, false, true, false><<<dim3(4, 64), 256>>>(
        pact, pwt + WT_FC2, fc2b, px1, out);
}